// round 17
// baseline (speedup 1.0000x reference)
#include <cuda_runtime.h>

typedef unsigned long long u64;

#define SEQ   20
#define FEAT  5
#define NU1   10
#define NU2   7
#define NU3   4
#define NOUT  4
#define NBATCH 262144
#define NTHREADS 128
#define EPB (NTHREADS * 2)      // 2 batch elements per thread
#define TCHUNK 5                // timesteps staged per smem chunk

// ---------------- packed f32x2 helpers ----------------
__device__ __forceinline__ u64 pack2(float lo, float hi) {
    u64 r; asm("mov.b64 %0, {%1, %2};" : "=l"(r) : "f"(lo), "f"(hi)); return r;
}
__device__ __forceinline__ u64 dup2(float s) {
    u64 r; asm("mov.b64 %0, {%1, %1};" : "=l"(r) : "f"(s)); return r;
}
__device__ __forceinline__ void unpack2(u64 v, float& lo, float& hi) {
    asm("mov.b64 {%0, %1}, %2;" : "=f"(lo), "=f"(hi) : "l"(v));
}
__device__ __forceinline__ u64 ffma2(u64 a, u64 b, u64 c) {
    u64 d; asm("fma.rn.f32x2 %0, %1, %2, %3;" : "=l"(d) : "l"(a), "l"(b), "l"(c)); return d;
}
__device__ __forceinline__ u64 fmul2(u64 a, u64 b) {
    u64 d; asm("mul.rn.f32x2 %0, %1, %2;" : "=l"(d) : "l"(a), "l"(b)); return d;
}

// ---------------- single-MUFU nonlinearities ----------------
__device__ __forceinline__ float tanh1(float x) {
    float y; asm("tanh.approx.f32 %0, %1;" : "=f"(y) : "f"(x)); return y;
}
__device__ __forceinline__ u64 tanh2(u64 v) {
    float a, b; unpack2(v, a, b);
    return pack2(tanh1(a), tanh1(b));
}
// sigmoid(x) = 0.5*tanh(x/2) + 0.5 ; the /2 pre-folded into i/f/o weights.
__device__ __forceinline__ u64 sigh2(u64 zhalf, u64 H2) {
    return ffma2(tanh2(zhalf), H2, H2);
}

// ---------------- shared-memory layout (float offsets, dynamic smem) ----------
constexpr int OFF_W1 = 0;      // 15 rows * 5 PH * 4 g * 2 = 600
constexpr int OFF_B1 = 600;    // 40
constexpr int OFF_W2 = 640;    // 17 * 4 * 4 * 2 = 544 (U2 cols padded 7->8)
constexpr int OFF_B2 = 1184;   // 32
constexpr int OFF_W3 = 1216;   // 11 * 2 * 4 * 2 = 176
constexpr int OFF_B3 = 1392;   // 16
constexpr int OFF_WD = 1408;   // 16
constexpr int OFF_BD = 1424;   // 4
constexpr int OFF_XS = 1428;   // x chunk: [EPB rows][TCHUNK*FEAT cols]
constexpr int XCOLS  = TCHUNK * FEAT;                       // 25
constexpr int OFF_CS = OFF_XS + EPB * XCOLS;                // c-state: 22 pairs x NT u64
constexpr int NCPAIR = 11;                                  // 5 + 4 + 2 pairs per element
constexpr int SMEM_FLOATS = OFF_CS + 2 * NCPAIR * NTHREADS * 2;
constexpr int SMEM_BYTES  = SMEM_FLOATS * 4;                // 53,840 B (x4 = 215 KB)

constexpr int CP_L1 = 0, CP_L2 = 5, CP_L3 = 9;

// gate scale: i,f,o get 0.5 (sigmoid-via-tanh), g(cell) gets 1.0
__device__ __forceinline__ float gate_scale(int g) { return (g == 2) ? 1.0f : 0.5f; }

__device__ __forceinline__ void load_wcomb(float* dst, const float* __restrict__ Wk,
                                           const float* __restrict__ Wr,
                                           int D, int U, int PH) {
    int total = (D + U) * PH * 4;
    for (int idx = threadIdx.x; idx < total; idx += blockDim.x) {
        int row = idx / (PH * 4);
        int rem = idx - row * (PH * 4);
        int p = rem >> 2, g = rem & 3;
        const float* src = (row < D) ? (Wk + row * 4 * U) : (Wr + (row - D) * 4 * U);
        float sc = gate_scale(g);
        int u0 = 2 * p, u1 = u0 + 1;
        dst[2 * idx]     = (u0 < U) ? sc * src[g * U + u0] : 0.0f;
        dst[2 * idx + 1] = (u1 < U) ? sc * src[g * U + u1] : 0.0f;
    }
}
__device__ __forceinline__ void load_bias(float* dst, const float* __restrict__ b,
                                          int U, int PH) {
    int total = PH * 4;
    for (int idx = threadIdx.x; idx < total; idx += blockDim.x) {
        int p = idx >> 2, g = idx & 3;
        float sc = gate_scale(g);
        int u0 = 2 * p, u1 = u0 + 1;
        dst[2 * idx]     = (u0 < U) ? sc * b[g * U + u0] : 0.0f;
        dst[2 * idx + 1] = (u1 < U) ? sc * b[g * U + u1] : 0.0f;
    }
}

// ---------------- LSTM layer step: 2 elements share every weight load --------
// p-loop NOT unrolled (contains register pressure); k-loop fully unrolled.
// din comes from REGISTER arrays (x hoisted by caller); c-state in smem
// (thread-private columns). h write guarded so U-sized arrays suffice.
template<int D, int U, int PH>
__device__ __forceinline__ void layer_step2(const float (&dA)[D], const float (&dB)[D],
                                            float* __restrict__ hA, float* __restrict__ hB,
                                            u64* __restrict__ csA, u64* __restrict__ csB,
                                            const float* __restrict__ w,
                                            const float* __restrict__ bias, u64 H2) {
    float oldA[U], oldB[U];
#pragma unroll
    for (int i = 0; i < U; i++) { oldA[i] = hA[i]; oldB[i] = hB[i]; }

#pragma unroll 1
    for (int p = 0; p < PH; p++) {
        u64 cOldA = csA[p * NTHREADS];
        u64 cOldB = csB[p * NTHREADS];
        ulonglong2 bv0 = *(const ulonglong2*)(bias + p * 8);
        ulonglong2 bv1 = *(const ulonglong2*)(bias + p * 8 + 4);
        u64 zaA = bv0.x, zfA = bv0.y, zgA = bv1.x, zoA = bv1.y;
        u64 zaB = bv0.x, zfB = bv0.y, zgB = bv1.x, zoB = bv1.y;
        const float* wp = w + p * 8;
#pragma unroll
        for (int k = 0; k < D + U; k++) {
            float sA = (k < D) ? dA[k] : oldA[k - D];
            float sB = (k < D) ? dB[k] : oldB[k - D];
            u64 mA = dup2(sA);
            u64 mB = dup2(sB);
            const float* row = wp + k * PH * 8;
            ulonglong2 w0 = *(const ulonglong2*)(row);
            ulonglong2 w1 = *(const ulonglong2*)(row + 4);
            zaA = ffma2(mA, w0.x, zaA); zfA = ffma2(mA, w0.y, zfA);
            zgA = ffma2(mA, w1.x, zgA); zoA = ffma2(mA, w1.y, zoA);
            zaB = ffma2(mB, w0.x, zaB); zfB = ffma2(mB, w0.y, zfB);
            zgB = ffma2(mB, w1.x, zgB); zoB = ffma2(mB, w1.y, zoB);
        }
        {
            u64 iv = sigh2(zaA, H2), fv = sigh2(zfA, H2), gv = tanh2(zgA), ov = sigh2(zoA, H2);
            u64 cn = ffma2(fv, cOldA, fmul2(iv, gv));
            csA[p * NTHREADS] = cn;
            float hlo, hhi;
            unpack2(fmul2(ov, tanh2(cn)), hlo, hhi);
            hA[2 * p] = hlo;
            if (2 * p + 1 < U) hA[2 * p + 1] = hhi;
        }
        {
            u64 iv = sigh2(zaB, H2), fv = sigh2(zfB, H2), gv = tanh2(zgB), ov = sigh2(zoB, H2);
            u64 cn = ffma2(fv, cOldB, fmul2(iv, gv));
            csB[p * NTHREADS] = cn;
            float hlo, hhi;
            unpack2(fmul2(ov, tanh2(cn)), hlo, hhi);
            hB[2 * p] = hlo;
            if (2 * p + 1 < U) hB[2 * p + 1] = hhi;
        }
    }
}

// array-reference adapters so h arrays can be passed as register arrays
template<int D, int U, int PH>
__device__ __forceinline__ void layer_step2_arr(const float (&dA)[D], const float (&dB)[D],
                                                float (&hA)[U], float (&hB)[U],
                                                u64* csA, u64* csB,
                                                const float* w, const float* bias, u64 H2) {
    layer_step2<D, U, PH>(dA, dB, (float*)hA, (float*)hB, csA, csB, w, bias, H2);
}

// ---------------- fused kernel ----------------
__global__ void __launch_bounds__(NTHREADS, 4)
lstm3_kernel(const float* __restrict__ x,
             const float* __restrict__ Wk1, const float* __restrict__ Wr1, const float* __restrict__ b1,
             const float* __restrict__ Wk2, const float* __restrict__ Wr2, const float* __restrict__ b2,
             const float* __restrict__ Wk3, const float* __restrict__ Wr3, const float* __restrict__ b3,
             const float* __restrict__ Wd,  const float* __restrict__ bd,
             float* __restrict__ out) {
    extern __shared__ float s[];

    load_wcomb(s + OFF_W1, Wk1, Wr1, FEAT, NU1, 5);
    load_bias (s + OFF_B1, b1, NU1, 5);
    load_wcomb(s + OFF_W2, Wk2, Wr2, NU1, NU2, 4);
    load_bias (s + OFF_B2, b2, NU2, 4);
    load_wcomb(s + OFF_W3, Wk3, Wr3, NU2, NU3, 2);
    load_bias (s + OFF_B3, b3, NU3, 2);
    for (int idx = threadIdx.x; idx < 8; idx += blockDim.x) {
        int k = idx >> 1, p = idx & 1;
        s[OFF_WD + 2 * idx]     = 0.5f * Wd[k * 4 + 2 * p];
        s[OFF_WD + 2 * idx + 1] = 0.5f * Wd[k * 4 + 2 * p + 1];
    }
    for (int idx = threadIdx.x; idx < 4; idx += blockDim.x)
        s[OFF_BD + idx] = 0.5f * bd[idx];
    __syncthreads();   // the ONLY block barrier: weights visible to all warps

    const int tid = threadIdx.x;
    const int wid = tid >> 5;
    const u64 H2 = pack2(0.5f, 0.5f);
    const float* gx = x + (size_t)blockIdx.x * EPB * (SEQ * FEAT);
    float* xs = s + OFF_XS;
    u64* cs = (u64*)(s + OFF_CS);
    u64* csA = cs + tid;                          // element A's c bank (own column)
    u64* csB = cs + NCPAIR * NTHREADS + tid;      // element B's c bank (own column)

    // zero own c columns (thread-private, no sync needed)
#pragma unroll
    for (int i = 0; i < NCPAIR; i++) { csA[i * NTHREADS] = 0ull; csB[i * NTHREADS] = 0ull; }

    const int gidA = blockIdx.x * EPB + tid;
    float* oA = out + (size_t)gidA * (SEQ * NOUT);
    float* oB = oA + (size_t)NTHREADS * (SEQ * NOUT);

    // h state: scalars in registers (h2 exactly 7 now, guarded writes)
    float h1A[NU1], h1B[NU1], h2A[NU2], h2B[NU2], h3A[NU3], h3B[NU3];
#pragma unroll
    for (int i = 0; i < NU1; i++) { h1A[i] = h1B[i] = 0.0f; }
#pragma unroll
    for (int i = 0; i < NU2; i++) { h2A[i] = h2B[i] = 0.0f; }
#pragma unroll
    for (int i = 0; i < NU3; i++) { h3A[i] = h3B[i] = 0.0f; }

#pragma unroll 1
    for (int cc = 0; cc < SEQ / TCHUNK; cc++) {
        // warp-private x staging: warp w owns rows [32w,32w+32) and [128+32w,128+32w+32),
        // exactly the rows its own threads consume -> __syncwarp suffices.
        __syncwarp();
        {
            const int lane = tid & 31;
            const int rbase0 = wid * 32;            // A rows of this warp
            const int rbase1 = 128 + wid * 32;      // B rows of this warp
            for (int i = lane; i < 32 * XCOLS; i += 32) {
                int rl = i / XCOLS, col = i - rl * XCOLS;
                int r0 = rbase0 + rl, r1 = rbase1 + rl;
                xs[r0 * XCOLS + col] = gx[r0 * (SEQ * FEAT) + cc * XCOLS + col];
                xs[r1 * XCOLS + col] = gx[r1 * (SEQ * FEAT) + cc * XCOLS + col];
            }
        }
        __syncwarp();

#pragma unroll
        for (int ts = 0; ts < TCHUNK; ts++) {
            int t = cc * TCHUNK + ts;
            // hoist x into registers ONCE per ts: kills the per-p smem re-reads
            // (ptxas can't hoist them itself past the aliasing c-state stores)
            float xA[FEAT], xB[FEAT];
#pragma unroll
            for (int k = 0; k < FEAT; k++) {
                xA[k] = xs[tid * XCOLS + ts * FEAT + k];
                xB[k] = xs[(tid + NTHREADS) * XCOLS + ts * FEAT + k];
            }

            layer_step2_arr<FEAT, NU1, 5>(xA,  xB,  h1A, h1B,
                                          csA + CP_L1 * NTHREADS, csB + CP_L1 * NTHREADS,
                                          s + OFF_W1, s + OFF_B1, H2);
            layer_step2_arr<NU1,  NU2, 4>(h1A, h1B, h2A, h2B,
                                          csA + CP_L2 * NTHREADS, csB + CP_L2 * NTHREADS,
                                          s + OFF_W2, s + OFF_B2, H2);
            layer_step2_arr<NU2,  NU3, 2>(h2A, h2B, h3A, h3B,
                                          csA + CP_L3 * NTHREADS, csB + CP_L3 * NTHREADS,
                                          s + OFF_W3, s + OFF_B3, H2);

            // dense 4x4 + sigmoid (weights pre-halved)
            ulonglong2 bdv = *(const ulonglong2*)(s + OFF_BD);
#pragma unroll
            for (int e = 0; e < 2; e++) {
                const float* h3 = e ? h3B : h3A;
                u64 z0 = bdv.x, z1 = bdv.y;
#pragma unroll
                for (int k = 0; k < NU3; k++) {
                    u64 m = dup2(h3[k]);
                    ulonglong2 w = *(const ulonglong2*)(s + OFF_WD + k * 4);
                    z0 = ffma2(m, w.x, z0);
                    z1 = ffma2(m, w.y, z1);
                }
                u64 r0 = sigh2(z0, H2), r1 = sigh2(z1, H2);
                float o0, o1, o2, o3;
                unpack2(r0, o0, o1);
                unpack2(r1, o2, o3);
                float* op = (e ? oB : oA) + t * NOUT;
                *(float4*)op = make_float4(o0, o1, o2, o3);
            }
        }
    }
}

extern "C" void kernel_launch(void* const* d_in, const int* in_sizes, int n_in,
                              void* d_out, int out_size) {
    const float* x   = (const float*)d_in[0];
    const float* Wk1 = (const float*)d_in[1];
    const float* Wr1 = (const float*)d_in[2];
    const float* b1  = (const float*)d_in[3];
    const float* Wk2 = (const float*)d_in[4];
    const float* Wr2 = (const float*)d_in[5];
    const float* b2  = (const float*)d_in[6];
    const float* Wk3 = (const float*)d_in[7];
    const float* Wr3 = (const float*)d_in[8];
    const float* b3  = (const float*)d_in[9];
    const float* Wd  = (const float*)d_in[10];
    const float* bd  = (const float*)d_in[11];

    cudaFuncSetAttribute(lstm3_kernel, cudaFuncAttributeMaxDynamicSharedMemorySize, SMEM_BYTES);

    lstm3_kernel<<<NBATCH / EPB, NTHREADS, SMEM_BYTES>>>(
        x, Wk1, Wr1, b1, Wk2, Wr2, b2, Wk3, Wr3, b3, Wd, bd, (float*)d_out);
}